// round 3
// baseline (speedup 1.0000x reference)
#include <cuda_runtime.h>
#include <math.h>

#define Bz    4
#define Nq    4097
#define CDIM  384
#define HEADS 8
#define HD    48
#define Msr   513

#define KSTR  56    // K smem row stride (words)  (56 % 32 == 24: phase-conflict-free)
#define VSTR  104   // paired V smem stride       (104 % 32 == 8)
#define PSTR  72    // paired P smem stride       (72 % 32 == 8)
#define ASTR  40    // gemm A smem stride         (40 % 32 == 8)
#define WSTR  40    // gemm W smem stride

// ---------------- scratch (static device globals; no allocs allowed) --------
__device__ float g_q   [(size_t)Bz * Nq  * CDIM];     // q (tf32 bits, pre-scaled)
__device__ float g_attn[(size_t)Bz * Nq  * CDIM];     // x_tf then attn out (tf32)
__device__ float g_xr  [(size_t)Bz * Msr * CDIM];     // reduced+LN tokens (tf32)
__device__ float g_kv  [(size_t)Bz * Msr * 2 * CDIM]; // K(col-permuted)/V (tf32)
__device__ float g_wtf [589824];                      // q_w | kv_w | proj_w (tf32)

// ---------------- tf32 helpers ----------------------------------------------
__device__ __forceinline__ unsigned f2tf(float f) {
    unsigned r;
    asm("cvt.rna.tf32.f32 %0, %1;" : "=r"(r) : "f"(f));
    return r;
}

__device__ __forceinline__ void mma_tf32(float* d, const unsigned* a,
                                         unsigned b0, unsigned b1) {
    asm volatile(
        "mma.sync.aligned.m16n8k8.row.col.f32.tf32.tf32.f32 "
        "{%0,%1,%2,%3}, {%4,%5,%6,%7}, {%8,%9}, {%0,%1,%2,%3};"
        : "+f"(d[0]), "+f"(d[1]), "+f"(d[2]), "+f"(d[3])
        : "r"(a[0]), "r"(a[1]), "r"(a[2]), "r"(a[3]), "r"(b0), "r"(b1));
}

// column permutation within 8-groups: j -> 2*(j&3) + (j>>2)  (pairs d,d+4 adjacent)
__device__ __forceinline__ int poscol(int c) {
    return (c & ~7) | (((c & 3) << 1) | ((c >> 2) & 1));
}

// ---------------- bulk fp32 -> tf32 conversion ------------------------------
__global__ __launch_bounds__(256)
void cvt_tf32_kernel(const float* __restrict__ s, float* __restrict__ d, int n4) {
    int i = blockIdx.x * 256 + threadIdx.x;
    if (i < n4) {
        float4 v = *(const float4*)&s[i * 4];
        uint4 u = make_uint4(f2tf(v.x), f2tf(v.y), f2tf(v.z), f2tf(v.w));
        *(uint4*)&d[i * 4] = u;
    }
}

// ---------------- fused depthwise-conv(2x2x2,s2) + CLS + LayerNorm ----------
__global__ __launch_bounds__(384)
void reduce_ln_kernel(const float* __restrict__ x,
                      const float* __restrict__ sr_w,
                      const float* __restrict__ sr_b,
                      const float* __restrict__ ln_g,
                      const float* __restrict__ ln_b) {
    int m = blockIdx.x;          // 0..512 (0 = CLS)
    int b = blockIdx.y;
    int c = threadIdx.x;         // 384 channels

    float val;
    if (m == 0) {
        val = x[(size_t)(b * Nq) * CDIM + c];
    } else {
        int p  = m - 1;
        int z0 = p >> 6, z1 = (p >> 3) & 7, z2 = p & 7;
        int base = 1 + (2 * z0) * 256 + (2 * z1) * 16 + (2 * z2);
        float acc = sr_b[c];
#pragma unroll
        for (int i = 0; i < 2; i++)
#pragma unroll
            for (int j = 0; j < 2; j++)
#pragma unroll
                for (int k = 0; k < 2; k++) {
                    int tok = base + i * 256 + j * 16 + k;
                    acc = fmaf(x[(size_t)(b * Nq + tok) * CDIM + c],
                               sr_w[c * 8 + i * 4 + j * 2 + k], acc);
                }
        val = acc;
    }

    __shared__ float s_sum[12], s_sq[12];
    float v1 = val, v2 = val * val;
#pragma unroll
    for (int off = 16; off > 0; off >>= 1) {
        v1 += __shfl_xor_sync(0xffffffffu, v1, off);
        v2 += __shfl_xor_sync(0xffffffffu, v2, off);
    }
    int warp = c >> 5, lane = c & 31;
    if (lane == 0) { s_sum[warp] = v1; s_sq[warp] = v2; }
    __syncthreads();
    float tot = 0.f, totsq = 0.f;
#pragma unroll
    for (int w = 0; w < 12; w++) { tot += s_sum[w]; totsq += s_sq[w]; }
    float mu  = tot * (1.0f / CDIM);
    float var = totsq * (1.0f / CDIM) - mu * mu;
    float y = (val - mu) * rsqrtf(var + 1e-5f) * ln_g[c] + ln_b[c];
    g_xr[(size_t)(b * Msr + m) * CDIM + c] = __uint_as_float(f2tf(y));
}

// ---------------- TF32 tensor-core GEMM (inputs pre-converted) ---------------
// C[M,N] = A[M,384] @ W[N,384]^T ; tiles BM=64, BN=128, BK=32; 8 warps
// MODE 0: KV epilogue (K column-permute + tf32)   MODE 1: Q (tf32 * scale)
// MODE 2: OUT (fp32 + bias)
#define GK 384
template<int MODE>
__global__ __launch_bounds__(256)
void gemm_tc(const unsigned* __restrict__ A, const unsigned* __restrict__ W,
             const float* __restrict__ bias, float* __restrict__ C,
             int Md, int Nd) {
    __shared__ unsigned As[64 * ASTR];
    __shared__ unsigned Ws[128 * WSTR];
    int tid = threadIdx.x;
    int warp = tid >> 5, lane = tid & 31;
    int g = lane >> 2, t = lane & 3;
    int wm = warp & 3, wn = warp >> 2;
    int m0 = blockIdx.y * 64, n0 = blockIdx.x * 128;

    float acc[8][4] = {};

    for (int k0 = 0; k0 < GK; k0 += 32) {
        // A tile (64x32), paired-column layout
#pragma unroll
        for (int i = 0; i < 2; i++) {
            int idx = tid + i * 256;
            int row = idx >> 3;
            int c4  = (idx & 7) * 4;
            uint4 v = make_uint4(0u, 0u, 0u, 0u);
            if (m0 + row < Md)
                v = *(const uint4*)&A[(size_t)(m0 + row) * GK + k0 + c4];
            int base = row * ASTR + ((c4 & ~7) | ((c4 & 4) >> 2));
            As[base + 0] = v.x; As[base + 2] = v.y;
            As[base + 4] = v.z; As[base + 6] = v.w;
        }
        // W tile (128x32), paired-column layout
#pragma unroll
        for (int i = 0; i < 4; i++) {
            int idx = tid + i * 256;
            int row = idx >> 3;
            int c4  = (idx & 7) * 4;
            uint4 v = *(const uint4*)&W[(size_t)(n0 + row) * GK + k0 + c4];
            int base = row * WSTR + ((c4 & ~7) | ((c4 & 4) >> 2));
            Ws[base + 0] = v.x; Ws[base + 2] = v.y;
            Ws[base + 4] = v.z; Ws[base + 6] = v.w;
        }
        __syncthreads();

#pragma unroll
        for (int kb = 0; kb < 4; kb++) {
            int ar = wm * 16 + g;
            uint2 a02 = *(const uint2*)&As[ar * ASTR + kb * 8 + 2 * t];
            uint2 a13 = *(const uint2*)&As[(ar + 8) * ASTR + kb * 8 + 2 * t];
            unsigned a[4] = {a02.x, a13.x, a02.y, a13.y};
#pragma unroll
            for (int nb = 0; nb < 8; nb++) {
                int bc = wn * 64 + nb * 8 + g;
                uint2 b01 = *(const uint2*)&Ws[bc * WSTR + kb * 8 + 2 * t];
                mma_tf32(acc[nb], a, b01.x, b01.y);
            }
        }
        __syncthreads();
    }

    // epilogue
#pragma unroll
    for (int nb = 0; nb < 8; nb++) {
        int col = n0 + wn * 64 + nb * 8 + 2 * t;
        int r = m0 + wm * 16 + g;
        if (MODE == 2) {
            float bx = bias[col], by = bias[col + 1];
            if (r < Md)
                *(float2*)&C[(size_t)r * Nd + col] =
                    make_float2(acc[nb][0] + bx, acc[nb][1] + by);
            if (r + 8 < Md)
                *(float2*)&C[(size_t)(r + 8) * Nd + col] =
                    make_float2(acc[nb][2] + bx, acc[nb][3] + by);
        } else if (MODE == 1) {
            const float SC = 0.14433756729740644f;   // 48^-0.5
            if (r < Md)
                *(float2*)&C[(size_t)r * Nd + col] =
                    make_float2(__uint_as_float(f2tf(acc[nb][0] * SC)),
                                __uint_as_float(f2tf(acc[nb][1] * SC)));
            if (r + 8 < Md)
                *(float2*)&C[(size_t)(r + 8) * Nd + col] =
                    make_float2(__uint_as_float(f2tf(acc[nb][2] * SC)),
                                __uint_as_float(f2tf(acc[nb][3] * SC)));
        } else {
            int oc0 = (col < CDIM) ? poscol(col) : col;
            int oc1 = (col + 1 < CDIM) ? poscol(col + 1) : col + 1;
            if (r < Md) {
                C[(size_t)r * Nd + oc0] = __uint_as_float(f2tf(acc[nb][0]));
                C[(size_t)r * Nd + oc1] = __uint_as_float(f2tf(acc[nb][1]));
            }
            if (r + 8 < Md) {
                C[(size_t)(r + 8) * Nd + oc0] = __uint_as_float(f2tf(acc[nb][2]));
                C[(size_t)(r + 8) * Nd + oc1] = __uint_as_float(f2tf(acc[nb][3]));
            }
        }
    }
}

// ---------------- TF32 tensor-core flash attention --------------------------
// CTA: 128 queries, 8 warps x 16 rows; key chunks of 64 staged in smem
__global__ __launch_bounds__(256)
void attn_tc_kernel() {
    extern __shared__ unsigned sm[];
    unsigned* ks = sm;                       // 64 * KSTR
    unsigned* vs = sm + 64 * KSTR;           // 32 * VSTR (paired rows)
    unsigned* ps = vs + 32 * VSTR;           // 8 * 16 * PSTR

    int tid = threadIdx.x;
    int warp = tid >> 5, lane = tid & 31;
    int g = lane >> 2, t = lane & 3;
    int h = blockIdx.y, b = blockIdx.z;
    int qbase = blockIdx.x * 128 + warp * 16;
    int r0 = qbase + g, r1 = r0 + 8;

    const unsigned* qarr = (const unsigned*)g_q;
    const unsigned* kvarr = (const unsigned*)g_kv;

    // Q fragments (pre-scaled tf32 from gmem; plain column order)
    unsigned qf[6][4];
    const unsigned* qp = qarr + (size_t)(b * Nq) * CDIM + h * HD;
#pragma unroll
    for (int kb = 0; kb < 6; kb++) {
        int c0 = kb * 8 + t;
        qf[kb][0] = (r0 < Nq) ? qp[(size_t)r0 * CDIM + c0] : 0u;
        qf[kb][1] = (r1 < Nq) ? qp[(size_t)r1 * CDIM + c0] : 0u;
        qf[kb][2] = (r0 < Nq) ? qp[(size_t)r0 * CDIM + c0 + 4] : 0u;
        qf[kb][3] = (r1 < Nq) ? qp[(size_t)r1 * CDIM + c0 + 4] : 0u;
    }

    float o[6][4] = {};
    float mx0 = -1e30f, mx1 = -1e30f, l0 = 0.f, l1 = 0.f;
    unsigned* pw = ps + warp * 16 * PSTR;

    for (int m0 = 0; m0 < Msr; m0 += 64) {
        // cooperative K copy (K already column-permuted + tf32 in gmem)
#pragma unroll
        for (int i = 0; i < 3; i++) {
            int u = tid + i * 256;           // 0..767 uint4
            int key = u / 12;
            int c4  = (u % 12) * 4;
            uint4 kval = make_uint4(0u, 0u, 0u, 0u);
            if (m0 + key < Msr)
                kval = *(const uint4*)&kvarr[(size_t)(b * Msr + m0 + key) * (2 * CDIM)
                                             + h * HD + c4];
            *(uint4*)&ks[key * KSTR + c4] = kval;
        }
        // cooperative V copy -> paired-row layout
#pragma unroll
        for (int i = 0; i < 3; i++) {
            int u = tid + i * 256;
            int key = u / 12;
            int c4  = (u % 12) * 4;
            uint4 vval = make_uint4(0u, 0u, 0u, 0u);
            if (m0 + key < Msr)
                vval = *(const uint4*)&kvarr[(size_t)(b * Msr + m0 + key) * (2 * CDIM)
                                             + CDIM + h * HD + c4];
            int prow = (key >> 3) * 4 + (key & 3);
            int half = (key >> 2) & 1;
            unsigned* vd = &vs[prow * VSTR + c4 * 2 + half];
            vd[0] = vval.x; vd[2] = vval.y; vd[4] = vval.z; vd[6] = vval.w;
        }
        __syncthreads();

        // S = Q @ K^T
        float s[8][4];
#pragma unroll
        for (int nb = 0; nb < 8; nb++) {
            s[nb][0] = s[nb][1] = s[nb][2] = s[nb][3] = 0.f;
            const unsigned* kr = &ks[(nb * 8 + g) * KSTR + 2 * t];
#pragma unroll
            for (int kb = 0; kb < 6; kb++) {
                uint2 b01 = *(const uint2*)&kr[kb * 8];
                mma_tf32(s[nb], qf[kb], b01.x, b01.y);
            }
        }

        // mask invalid keys + chunk row max
        float cm0 = -1e30f, cm1 = -1e30f;
#pragma unroll
        for (int nb = 0; nb < 8; nb++) {
            int key = m0 + nb * 8 + 2 * t;
            if (key >= Msr)     s[nb][0] = s[nb][2] = -1e30f;
            if (key + 1 >= Msr) s[nb][1] = s[nb][3] = -1e30f;
            cm0 = fmaxf(cm0, fmaxf(s[nb][0], s[nb][1]));
            cm1 = fmaxf(cm1, fmaxf(s[nb][2], s[nb][3]));
        }
        cm0 = fmaxf(cm0, __shfl_xor_sync(0xffffffffu, cm0, 1));
        cm0 = fmaxf(cm0, __shfl_xor_sync(0xffffffffu, cm0, 2));
        cm1 = fmaxf(cm1, __shfl_xor_sync(0xffffffffu, cm1, 1));
        cm1 = fmaxf(cm1, __shfl_xor_sync(0xffffffffu, cm1, 2));

        float nm0 = fmaxf(mx0, cm0), nm1 = fmaxf(mx1, cm1);
        float corr0 = __expf(mx0 - nm0), corr1 = __expf(mx1 - nm1);
        mx0 = nm0; mx1 = nm1;

        // P = exp(S - m) -> paired-column smem; accumulate row sums
        int c0 = 2 * t, c1 = 2 * t + 1;
        int pp0 = ((c0 & 3) << 1) | (c0 >> 2);
        int pp1 = ((c1 & 3) << 1) | (c1 >> 2);
        float sum0 = 0.f, sum1 = 0.f;
#pragma unroll
        for (int nb = 0; nb < 8; nb++) {
            float p0 = __expf(s[nb][0] - nm0);
            float p1 = __expf(s[nb][1] - nm0);
            float p2 = __expf(s[nb][2] - nm1);
            float p3 = __expf(s[nb][3] - nm1);
            sum0 += p0 + p1; sum1 += p2 + p3;
            pw[g * PSTR + nb * 8 + pp0]       = f2tf(p0);
            pw[g * PSTR + nb * 8 + pp1]       = f2tf(p1);
            pw[(g + 8) * PSTR + nb * 8 + pp0] = f2tf(p2);
            pw[(g + 8) * PSTR + nb * 8 + pp1] = f2tf(p3);
        }
        sum0 += __shfl_xor_sync(0xffffffffu, sum0, 1);
        sum0 += __shfl_xor_sync(0xffffffffu, sum0, 2);
        sum1 += __shfl_xor_sync(0xffffffffu, sum1, 1);
        sum1 += __shfl_xor_sync(0xffffffffu, sum1, 2);
        l0 = l0 * corr0 + sum0;
        l1 = l1 * corr1 + sum1;

#pragma unroll
        for (int nb = 0; nb < 6; nb++) {
            o[nb][0] *= corr0; o[nb][1] *= corr0;
            o[nb][2] *= corr1; o[nb][3] *= corr1;
        }
        __syncwarp();

        // O += P @ V
#pragma unroll
        for (int kb = 0; kb < 8; kb++) {
            uint2 p02 = *(const uint2*)&pw[g * PSTR + kb * 8 + 2 * t];
            uint2 p13 = *(const uint2*)&pw[(g + 8) * PSTR + kb * 8 + 2 * t];
            unsigned a[4] = {p02.x, p13.x, p02.y, p13.y};
            const unsigned* vr = &vs[(kb * 4 + t) * VSTR];
#pragma unroll
            for (int nb = 0; nb < 6; nb++) {
                uint2 b01 = *(const uint2*)&vr[(nb * 8 + g) * 2];
                mma_tf32(o[nb], a, b01.x, b01.y);
            }
        }
        __syncthreads();
    }

    // epilogue -> tf32 bits (consumed by out-proj GEMM)
    float i0 = 1.f / l0, i1 = 1.f / l1;
    float* op = g_attn + (size_t)(b * Nq) * CDIM + h * HD;
#pragma unroll
    for (int nb = 0; nb < 6; nb++) {
        int col = nb * 8 + 2 * t;
        if (r0 < Nq)
            *(float2*)&op[(size_t)r0 * CDIM + col] =
                make_float2(__uint_as_float(f2tf(o[nb][0] * i0)),
                            __uint_as_float(f2tf(o[nb][1] * i0)));
        if (r1 < Nq)
            *(float2*)&op[(size_t)r1 * CDIM + col] =
                make_float2(__uint_as_float(f2tf(o[nb][2] * i1)),
                            __uint_as_float(f2tf(o[nb][3] * i1)));
    }
}

// ---------------- launcher ---------------------------------------------------
extern "C" void kernel_launch(void* const* d_in, const int* in_sizes, int n_in,
                              void* d_out, int out_size) {
    const float* x      = (const float*)d_in[0];
    const float* q_w    = (const float*)d_in[1];
    const float* kv_w   = (const float*)d_in[2];
    const float* proj_w = (const float*)d_in[3];
    const float* proj_b = (const float*)d_in[4];
    const float* sr_w   = (const float*)d_in[5];
    const float* sr_b   = (const float*)d_in[6];
    const float* ln_g   = (const float*)d_in[7];
    const float* ln_b   = (const float*)d_in[8];
    float* out = (float*)d_out;

    float *qb, *xrb, *kvb, *atb, *wtf;
    cudaGetSymbolAddress((void**)&qb,  g_q);
    cudaGetSymbolAddress((void**)&xrb, g_xr);
    cudaGetSymbolAddress((void**)&kvb, g_kv);
    cudaGetSymbolAddress((void**)&atb, g_attn);
    cudaGetSymbolAddress((void**)&wtf, g_wtf);

    const int Mq = Bz * Nq;        // 16388
    const int Mr = Bz * Msr;       // 2052
    const int smem_attn = (64 * KSTR + 32 * VSTR + 8 * 16 * PSTR) * 4;

    static int cfg_done = 0;
    cudaFuncSetAttribute(attn_tc_kernel,
                         cudaFuncAttributeMaxDynamicSharedMemorySize, smem_attn);
    (void)cfg_done;

    // 0. pre-convert x and weights to tf32 bits
    cvt_tf32_kernel<<<(Mq * CDIM / 4 + 255) / 256, 256>>>(x, atb, Mq * CDIM / 4);
    cvt_tf32_kernel<<<(147456 / 4 + 255) / 256, 256>>>(q_w, wtf, 147456 / 4);
    cvt_tf32_kernel<<<(294912 / 4 + 255) / 256, 256>>>(kv_w, wtf + 147456, 294912 / 4);
    cvt_tf32_kernel<<<(147456 / 4 + 255) / 256, 256>>>(proj_w, wtf + 442368, 147456 / 4);
    // 1. reduced tokens + LN (tf32 out)
    reduce_ln_kernel<<<dim3(Msr, Bz), 384>>>(x, sr_w, sr_b, ln_g, ln_b);
    // 2. kv projection (K column-permuted + tf32)
    gemm_tc<0><<<dim3(768 / 128, (Mr + 63) / 64), 256>>>(
        (const unsigned*)xrb, (const unsigned*)(wtf + 147456), nullptr, kvb, Mr, 2 * CDIM);
    // 3. q projection (tf32 * scale)
    gemm_tc<1><<<dim3(CDIM / 128, (Mq + 63) / 64), 256>>>(
        (const unsigned*)atb, (const unsigned*)wtf, nullptr, qb, Mq, CDIM);
    // 4. attention (tensor-core flash)
    attn_tc_kernel<<<dim3((Nq + 127) / 128, HEADS, Bz), 256, smem_attn>>>();
    // 5. output projection + bias (fp32 out)
    gemm_tc<2><<<dim3(CDIM / 128, (Mq + 63) / 64), 256>>>(
        (const unsigned*)atb, (const unsigned*)(wtf + 442368), proj_b, out, Mq, CDIM);
}

// round 4
// speedup vs baseline: 1.5904x; 1.5904x over previous
#include <cuda_runtime.h>
#include <cuda_fp16.h>
#include <math.h>

#define Bz    4
#define Nq    4097
#define CDIM  384
#define HEADS 8
#define HD    48
#define Msr   513
#define KEYPAD 576          // padded key dim for V^T (covers last 64-key chunk)

// ---------------- scratch (static device globals; no allocs allowed) --------
__device__ __half g_xh[(size_t)Bz * Nq  * CDIM];       // x in fp16
__device__ __half g_qh[(size_t)Bz * Nq  * CDIM];       // q (pre-scaled) fp16
__device__ __half g_ah[(size_t)Bz * Nq  * CDIM];       // attention out fp16
__device__ __half g_xr[(size_t)Bz * Msr * CDIM];       // reduced+LN tokens fp16
__device__ __half g_kh[(size_t)Bz * Msr * CDIM];       // K fp16  [b*Msr][384]
__device__ __half g_vt[(size_t)Bz * HEADS * HD * KEYPAD]; // V^T fp16 [b][h][d][key]
__device__ __half g_wh[589824];                        // q_w*sc | kv_w | proj_w fp16

// ---------------- helpers ----------------------------------------------------
__device__ __forceinline__ unsigned packh2(float x, float y) {
    __half2 h = __floats2half2_rn(x, y);
    return *(unsigned*)&h;
}

__device__ __forceinline__ void mma_f16(float* d, const unsigned* a,
                                        unsigned b0, unsigned b1) {
    asm volatile(
        "mma.sync.aligned.m16n8k16.row.col.f32.f16.f16.f32 "
        "{%0,%1,%2,%3}, {%4,%5,%6,%7}, {%8,%9}, {%0,%1,%2,%3};"
        : "+f"(d[0]), "+f"(d[1]), "+f"(d[2]), "+f"(d[3])
        : "r"(a[0]), "r"(a[1]), "r"(a[2]), "r"(a[3]), "r"(b0), "r"(b1));
}

// ---------------- bulk fp32 -> fp16 (optional scale) -------------------------
__global__ __launch_bounds__(256)
void cvt_h_kernel(const float* __restrict__ s, __half* __restrict__ d,
                  int n4, float sc) {
    int i = blockIdx.x * 256 + threadIdx.x;
    if (i < n4) {
        float4 v = *(const float4*)&s[i * 4];
        uint2 u = make_uint2(packh2(v.x * sc, v.y * sc),
                             packh2(v.z * sc, v.w * sc));
        *(uint2*)&d[i * 4] = u;
    }
}

// ---------------- fused depthwise-conv(2x2x2,s2) + CLS + LayerNorm ----------
__global__ __launch_bounds__(384)
void reduce_ln_kernel(const float* __restrict__ x,
                      const float* __restrict__ sr_w,
                      const float* __restrict__ sr_b,
                      const float* __restrict__ ln_g,
                      const float* __restrict__ ln_b) {
    int m = blockIdx.x;          // 0..512 (0 = CLS)
    int b = blockIdx.y;
    int c = threadIdx.x;         // 384 channels

    float val;
    if (m == 0) {
        val = x[(size_t)(b * Nq) * CDIM + c];
    } else {
        int p  = m - 1;
        int z0 = p >> 6, z1 = (p >> 3) & 7, z2 = p & 7;
        int base = 1 + (2 * z0) * 256 + (2 * z1) * 16 + (2 * z2);
        float acc = sr_b[c];
#pragma unroll
        for (int i = 0; i < 2; i++)
#pragma unroll
            for (int j = 0; j < 2; j++)
#pragma unroll
                for (int k = 0; k < 2; k++) {
                    int tok = base + i * 256 + j * 16 + k;
                    acc = fmaf(x[(size_t)(b * Nq + tok) * CDIM + c],
                               sr_w[c * 8 + i * 4 + j * 2 + k], acc);
                }
        val = acc;
    }

    __shared__ float s_sum[12], s_sq[12];
    float v1 = val, v2 = val * val;
#pragma unroll
    for (int off = 16; off > 0; off >>= 1) {
        v1 += __shfl_xor_sync(0xffffffffu, v1, off);
        v2 += __shfl_xor_sync(0xffffffffu, v2, off);
    }
    int warp = c >> 5, lane = c & 31;
    if (lane == 0) { s_sum[warp] = v1; s_sq[warp] = v2; }
    __syncthreads();
    float tot = 0.f, totsq = 0.f;
#pragma unroll
    for (int w = 0; w < 12; w++) { tot += s_sum[w]; totsq += s_sq[w]; }
    float mu  = tot * (1.0f / CDIM);
    float var = totsq * (1.0f / CDIM) - mu * mu;
    float y = (val - mu) * rsqrtf(var + 1e-5f) * ln_g[c] + ln_b[c];
    g_xr[(size_t)(b * Msr + m) * CDIM + c] = __float2half_rn(y);
}

// ---------------- fp16 tensor-core GEMM: C[M,N] = A[M,384] @ W[N,384]^T -----
// tiles BM=64, BN=128, BK=32 halves; 8 warps (4 M x 2 N)
// MODE 0: KV epilogue (K half / V^T scatter)  MODE 1: half out  MODE 2: fp32+bias
#define GK   384
#define GSTR 40     // smem row stride in halves (20 words; 20g+t conflict-free)
template<int MODE>
__global__ __launch_bounds__(256)
void gemm_h(const __half* __restrict__ A, const __half* __restrict__ W,
            const float* __restrict__ bias, void* __restrict__ Cout,
            int Md, int Nd) {
    __shared__ __half As[64 * GSTR];
    __shared__ __half Ws[128 * GSTR];
    int tid = threadIdx.x;
    int warp = tid >> 5, lane = tid & 31;
    int g = lane >> 2, t = lane & 3;
    int wm = warp & 3, wn = warp >> 2;
    int m0 = blockIdx.y * 64, n0 = blockIdx.x * 128;

    float acc[8][4] = {};

    for (int k0 = 0; k0 < GK; k0 += 32) {
        {   // A tile 64x32 halves: one uint4 (8 halves) per thread
            int row = tid >> 2, c8 = (tid & 3) * 8;
            uint4 v = make_uint4(0u, 0u, 0u, 0u);
            if (m0 + row < Md)
                v = *(const uint4*)&A[(size_t)(m0 + row) * GK + k0 + c8];
            *(uint4*)&As[row * GSTR + c8] = v;
        }
#pragma unroll
        for (int i = 0; i < 2; i++) {   // W tile 128x32 halves
            int idx = tid + i * 256;
            int row = idx >> 2, c8 = (idx & 3) * 8;
            uint4 v = *(const uint4*)&W[(size_t)(n0 + row) * GK + k0 + c8];
            *(uint4*)&Ws[row * GSTR + c8] = v;
        }
        __syncthreads();

#pragma unroll
        for (int kb = 0; kb < 2; kb++) {
            unsigned a[4];
            const unsigned* ar0 = (const unsigned*)&As[(wm * 16 + g) * GSTR + kb * 16];
            const unsigned* ar1 = (const unsigned*)&As[(wm * 16 + g + 8) * GSTR + kb * 16];
            a[0] = ar0[t]; a[1] = ar1[t]; a[2] = ar0[t + 4]; a[3] = ar1[t + 4];
#pragma unroll
            for (int nb = 0; nb < 8; nb++) {
                const unsigned* br = (const unsigned*)&Ws[(wn * 64 + nb * 8 + g) * GSTR + kb * 16];
                mma_f16(acc[nb], a, br[t], br[t + 4]);
            }
        }
        __syncthreads();
    }

    // epilogue
#pragma unroll
    for (int nb = 0; nb < 8; nb++) {
        int col = n0 + wn * 64 + nb * 8 + 2 * t;
        int r = m0 + wm * 16 + g;
        if (MODE == 2) {
            float* C = (float*)Cout;
            float bx = bias[col], by = bias[col + 1];
            if (r < Md)
                *(float2*)&C[(size_t)r * Nd + col] =
                    make_float2(acc[nb][0] + bx, acc[nb][1] + by);
            if (r + 8 < Md)
                *(float2*)&C[(size_t)(r + 8) * Nd + col] =
                    make_float2(acc[nb][2] + bx, acc[nb][3] + by);
        } else if (MODE == 1) {
            __half* C = (__half*)Cout;
            if (r < Md)
                *(unsigned*)&C[(size_t)r * Nd + col] = packh2(acc[nb][0], acc[nb][1]);
            if (r + 8 < Md)
                *(unsigned*)&C[(size_t)(r + 8) * Nd + col] = packh2(acc[nb][2], acc[nb][3]);
        } else {
            // kv: cols [0,384) -> K rows [b*Msr+key][384]; cols [384,768) -> V^T
            if (col < CDIM) {
                if (r < Md)
                    *(unsigned*)&g_kh[(size_t)r * CDIM + col] = packh2(acc[nb][0], acc[nb][1]);
                if (r + 8 < Md)
                    *(unsigned*)&g_kh[(size_t)(r + 8) * CDIM + col] = packh2(acc[nb][2], acc[nb][3]);
            } else {
#pragma unroll
                for (int e = 0; e < 4; e++) {
                    int rr = r + (e >= 2 ? 8 : 0);
                    if (rr >= Md) continue;
                    int cc = col + (e & 1);
                    int dall = cc - CDIM;
                    int hh = dall / HD, dd = dall % HD;
                    int bb = rr / Msr, key = rr % Msr;
                    g_vt[(((size_t)(bb * HEADS + hh) * HD) + dd) * KEYPAD + key] =
                        __float2half_rn(acc[nb][e]);
                }
            }
        }
    }
}

// ---------------- fp16 tensor-core flash attention ---------------------------
// CTA: 128 queries, 8 warps x 16 rows; 64-key chunks; P stays in registers
#define KSTRH 72    // K smem stride (halves) -> 36 words, 36g+t conflict-free
#define VSTRH 72    // V^T smem stride (halves)
__global__ __launch_bounds__(256)
void attn_h_kernel() {
    __shared__ __half ks[64 * KSTRH];
    __shared__ __half vt[HD * VSTRH];

    int tid = threadIdx.x;
    int warp = tid >> 5, lane = tid & 31;
    int g = lane >> 2, t = lane & 3;
    int h = blockIdx.y, b = blockIdx.z;
    int qbase = blockIdx.x * 128 + warp * 16;
    int r0 = qbase + g, r1 = r0 + 8;

    // Q fragments (pre-scaled fp16 from gmem)
    unsigned qf[3][4];
    const __half* qp = g_qh + (size_t)(b * Nq) * CDIM + h * HD;
#pragma unroll
    for (int kb = 0; kb < 3; kb++) {
        int c0 = kb * 16 + 2 * t;
        qf[kb][0] = (r0 < Nq) ? *(const unsigned*)&qp[(size_t)r0 * CDIM + c0] : 0u;
        qf[kb][1] = (r1 < Nq) ? *(const unsigned*)&qp[(size_t)r1 * CDIM + c0] : 0u;
        qf[kb][2] = (r0 < Nq) ? *(const unsigned*)&qp[(size_t)r0 * CDIM + c0 + 8] : 0u;
        qf[kb][3] = (r1 < Nq) ? *(const unsigned*)&qp[(size_t)r1 * CDIM + c0 + 8] : 0u;
    }

    float o[6][4] = {};
    float mx0 = -1e30f, mx1 = -1e30f, l0 = 0.f, l1 = 0.f;

    for (int m0 = 0; m0 < Msr; m0 += 64) {
        // K fill: 64 keys x 48 halves (6 uint4 per key)
        for (int u = tid; u < 64 * 6; u += 256) {
            int key = u / 6, c8 = (u % 6) * 8;
            uint4 v = make_uint4(0u, 0u, 0u, 0u);
            if (m0 + key < Msr)
                v = *(const uint4*)&g_kh[(size_t)(b * Msr + m0 + key) * CDIM + h * HD + c8];
            *(uint4*)&ks[key * KSTRH + c8] = v;
        }
        // V^T fill: 48 d-rows x 64 keys (8 uint4 per row); pad keys read zeros
        for (int u = tid; u < HD * 8; u += 256) {
            int d = u >> 3, c8 = (u & 7) * 8;
            uint4 v = *(const uint4*)&g_vt[(((size_t)(b * HEADS + h) * HD) + d) * KEYPAD + m0 + c8];
            *(uint4*)&vt[d * VSTRH + c8] = v;
        }
        __syncthreads();

        // S = Q @ K^T  (24 mma)
        float s[8][4];
#pragma unroll
        for (int nb = 0; nb < 8; nb++) {
            s[nb][0] = s[nb][1] = s[nb][2] = s[nb][3] = 0.f;
            const unsigned* kr = (const unsigned*)&ks[(nb * 8 + g) * KSTRH];
#pragma unroll
            for (int kb = 0; kb < 3; kb++)
                mma_f16(s[nb], qf[kb], kr[kb * 8 + t], kr[kb * 8 + t + 4]);
        }

        // mask invalid keys + chunk row max
        float cm0 = -1e30f, cm1 = -1e30f;
#pragma unroll
        for (int nb = 0; nb < 8; nb++) {
            int key = m0 + nb * 8 + 2 * t;
            if (key >= Msr)     s[nb][0] = s[nb][2] = -1e30f;
            if (key + 1 >= Msr) s[nb][1] = s[nb][3] = -1e30f;
            cm0 = fmaxf(cm0, fmaxf(s[nb][0], s[nb][1]));
            cm1 = fmaxf(cm1, fmaxf(s[nb][2], s[nb][3]));
        }
        cm0 = fmaxf(cm0, __shfl_xor_sync(0xffffffffu, cm0, 1));
        cm0 = fmaxf(cm0, __shfl_xor_sync(0xffffffffu, cm0, 2));
        cm1 = fmaxf(cm1, __shfl_xor_sync(0xffffffffu, cm1, 1));
        cm1 = fmaxf(cm1, __shfl_xor_sync(0xffffffffu, cm1, 2));

        float nm0 = fmaxf(mx0, cm0), nm1 = fmaxf(mx1, cm1);
        float corr0 = __expf(mx0 - nm0), corr1 = __expf(mx1 - nm1);
        mx0 = nm0; mx1 = nm1;

        // P = exp(S - m) packed to fp16 registers (matches A-fragment layout)
        unsigned ph01[8], ph23[8];
        float sum0 = 0.f, sum1 = 0.f;
#pragma unroll
        for (int nb = 0; nb < 8; nb++) {
            float p0 = __expf(s[nb][0] - nm0);
            float p1 = __expf(s[nb][1] - nm0);
            float p2 = __expf(s[nb][2] - nm1);
            float p3 = __expf(s[nb][3] - nm1);
            sum0 += p0 + p1; sum1 += p2 + p3;
            ph01[nb] = packh2(p0, p1);
            ph23[nb] = packh2(p2, p3);
        }
        sum0 += __shfl_xor_sync(0xffffffffu, sum0, 1);
        sum0 += __shfl_xor_sync(0xffffffffu, sum0, 2);
        sum1 += __shfl_xor_sync(0xffffffffu, sum1, 1);
        sum1 += __shfl_xor_sync(0xffffffffu, sum1, 2);
        l0 = l0 * corr0 + sum0;
        l1 = l1 * corr1 + sum1;

#pragma unroll
        for (int nb = 0; nb < 6; nb++) {
            o[nb][0] *= corr0; o[nb][1] *= corr0;
            o[nb][2] *= corr1; o[nb][3] *= corr1;
        }

        // O += P @ V  (24 mma, P from registers, V^T from smem)
#pragma unroll
        for (int kb = 0; kb < 4; kb++) {
            unsigned a[4] = {ph01[2 * kb], ph23[2 * kb], ph01[2 * kb + 1], ph23[2 * kb + 1]};
#pragma unroll
            for (int nb = 0; nb < 6; nb++) {
                const unsigned* vr = (const unsigned*)&vt[(nb * 8 + g) * VSTRH];
                mma_f16(o[nb], a, vr[kb * 8 + t], vr[kb * 8 + t + 4]);
            }
        }
        __syncthreads();
    }

    // epilogue -> fp16 (consumed by out-proj GEMM)
    float i0 = 1.f / l0, i1 = 1.f / l1;
    __half* op = g_ah + (size_t)(b * Nq) * CDIM + h * HD;
#pragma unroll
    for (int nb = 0; nb < 6; nb++) {
        int col = nb * 8 + 2 * t;
        if (r0 < Nq)
            *(unsigned*)&op[(size_t)r0 * CDIM + col] = packh2(o[nb][0] * i0, o[nb][1] * i0);
        if (r1 < Nq)
            *(unsigned*)&op[(size_t)r1 * CDIM + col] = packh2(o[nb][2] * i1, o[nb][3] * i1);
    }
}

// ---------------- launcher ---------------------------------------------------
extern "C" void kernel_launch(void* const* d_in, const int* in_sizes, int n_in,
                              void* d_out, int out_size) {
    const float* x      = (const float*)d_in[0];
    const float* q_w    = (const float*)d_in[1];
    const float* kv_w   = (const float*)d_in[2];
    const float* proj_w = (const float*)d_in[3];
    const float* proj_b = (const float*)d_in[4];
    const float* sr_w   = (const float*)d_in[5];
    const float* sr_b   = (const float*)d_in[6];
    const float* ln_g   = (const float*)d_in[7];
    const float* ln_b   = (const float*)d_in[8];
    float* out = (float*)d_out;

    __half *xh, *qh, *ah, *xr, *wh;
    cudaGetSymbolAddress((void**)&xh, g_xh);
    cudaGetSymbolAddress((void**)&qh, g_qh);
    cudaGetSymbolAddress((void**)&ah, g_ah);
    cudaGetSymbolAddress((void**)&xr, g_xr);
    cudaGetSymbolAddress((void**)&wh, g_wh);

    const int Mq = Bz * Nq;        // 16388
    const int Mr = Bz * Msr;       // 2052
    const float SC = 0.14433756729740644f;   // 48^-0.5

    // 0. pre-convert x + weights to fp16 (scale folded into q_w)
    cvt_h_kernel<<<(Mq * CDIM / 4 + 255) / 256, 256>>>(x, xh, Mq * CDIM / 4, 1.0f);
    cvt_h_kernel<<<(147456 / 4 + 255) / 256, 256>>>(q_w, wh, 147456 / 4, SC);
    cvt_h_kernel<<<(294912 / 4 + 255) / 256, 256>>>(kv_w, wh + 147456, 294912 / 4, 1.0f);
    cvt_h_kernel<<<(147456 / 4 + 255) / 256, 256>>>(proj_w, wh + 442368, 147456 / 4, 1.0f);
    // 1. reduced tokens + LN (fp16 out)
    reduce_ln_kernel<<<dim3(Msr, Bz), 384>>>(x, sr_w, sr_b, ln_g, ln_b);
    // 2. kv projection -> K halves + V^T scatter
    gemm_h<0><<<dim3(768 / 128, (Mr + 63) / 64), 256>>>(
        xr, wh + 147456, nullptr, nullptr, Mr, 2 * CDIM);
    // 3. q projection (scale pre-folded) -> fp16
    gemm_h<1><<<dim3(CDIM / 128, (Mq + 63) / 64), 256>>>(
        xh, wh, nullptr, qh, Mq, CDIM);
    // 4. attention
    attn_h_kernel<<<dim3((Nq + 127) / 128, HEADS, Bz), 256>>>();
    // 5. output projection + bias (fp32 out)
    gemm_h<2><<<dim3(CDIM / 128, (Mq + 63) / 64), 256>>>(
        ah, wh + 442368, proj_b, out, Mq, CDIM);
}

// round 6
// speedup vs baseline: 2.2772x; 1.4318x over previous
#include <cuda_runtime.h>
#include <cuda_fp16.h>
#include <cstdint>
#include <math.h>

#define Bz     4
#define Nq     4097
#define CDIM   384
#define HEADS  8
#define HD     48
#define Msr    513
#define KEYPAD 576
#define MPAD   16448        // padded query-row count (multiple of 64)
#define MRPAD  2112         // padded reduced-row count

// ---------------- scratch (static device globals; zero-init, no allocs) -----
__device__ __half g_xh[(size_t)MPAD * CDIM];            // x fp16 (rows padded)
__device__ __half g_qh[(size_t)MPAD * CDIM];            // q (scale*log2e folded)
__device__ __half g_ah[(size_t)MPAD * CDIM];            // attention out fp16
__device__ __half g_xr[(size_t)MRPAD * CDIM];           // reduced+LN tokens
__device__ __half g_kh[(size_t)Bz * KEYPAD * CDIM];     // K fp16, key-padded
__device__ __half g_vt[(size_t)Bz * HEADS * HD * KEYPAD]; // V^T fp16, key-padded
__device__ __half g_wh[589824];                         // q_w*sc | kv_w | proj_w

// ---------------- helpers ----------------------------------------------------
__device__ __forceinline__ unsigned packh2(float x, float y) {
    __half2 h = __floats2half2_rn(x, y);
    return *(unsigned*)&h;
}
__device__ __forceinline__ float ex2(float x) {
    float y;
    asm("ex2.approx.ftz.f32 %0, %1;" : "=f"(y) : "f"(x));
    return y;
}
__device__ __forceinline__ void mma_f16(float* d, const unsigned* a,
                                        unsigned b0, unsigned b1) {
    asm volatile(
        "mma.sync.aligned.m16n8k16.row.col.f32.f16.f16.f32 "
        "{%0,%1,%2,%3}, {%4,%5,%6,%7}, {%8,%9}, {%0,%1,%2,%3};"
        : "+f"(d[0]), "+f"(d[1]), "+f"(d[2]), "+f"(d[3])
        : "r"(a[0]), "r"(a[1]), "r"(a[2]), "r"(a[3]), "r"(b0), "r"(b1));
}
__device__ __forceinline__ void cp16(unsigned s, const void* g) {
    asm volatile("cp.async.cg.shared.global [%0], [%1], 16;" :: "r"(s), "l"(g));
}
#define CPCOMMIT() asm volatile("cp.async.commit_group;" ::: "memory")
template<int N>
__device__ __forceinline__ void cpwait() {
    asm volatile("cp.async.wait_group %0;" :: "n"(N) : "memory");
}

// ---------------- merged fp32 -> fp16 conversion -----------------------------
#define XC4 ((Bz * Nq * CDIM) / 4)
#define QC4 36864
#define KC4 73728
#define PC4 36864
__global__ __launch_bounds__(256)
void cvt_all(const float* __restrict__ x, const float* __restrict__ qw,
             const float* __restrict__ kvw, const float* __restrict__ pw) {
    int j = blockIdx.x * 256 + threadIdx.x;
    const float* s; __half* d;
    float sc = 1.f;
    if (j < XC4) { s = x; d = g_xh; }
    else {
        j -= XC4;
        if (j < QC4) { s = qw; d = g_wh;
                       sc = 0.14433756729740644f * 1.4426950408889634f; }
        else {
            j -= QC4;
            if (j < KC4) { s = kvw; d = g_wh + 147456; }
            else { j -= KC4; if (j >= PC4) return; s = pw; d = g_wh + 442368; }
        }
    }
    float4 v = *(const float4*)&s[(size_t)j * 4];
    uint2 u = make_uint2(packh2(v.x * sc, v.y * sc), packh2(v.z * sc, v.w * sc));
    *(uint2*)&d[(size_t)j * 4] = u;
}

// ---------------- fused depthwise-conv(2x2x2,s2) + CLS + LayerNorm ----------
__global__ __launch_bounds__(384)
void reduce_ln_kernel(const float* __restrict__ x,
                      const float* __restrict__ sr_w,
                      const float* __restrict__ sr_b,
                      const float* __restrict__ ln_g,
                      const float* __restrict__ ln_b) {
    int m = blockIdx.x, b = blockIdx.y, c = threadIdx.x;
    float val;
    if (m == 0) {
        val = x[(size_t)(b * Nq) * CDIM + c];
    } else {
        int p  = m - 1;
        int z0 = p >> 6, z1 = (p >> 3) & 7, z2 = p & 7;
        int base = 1 + (2 * z0) * 256 + (2 * z1) * 16 + (2 * z2);
        float acc = sr_b[c];
#pragma unroll
        for (int i = 0; i < 2; i++)
#pragma unroll
            for (int j = 0; j < 2; j++)
#pragma unroll
                for (int k = 0; k < 2; k++) {
                    int tok = base + i * 256 + j * 16 + k;
                    acc = fmaf(x[(size_t)(b * Nq + tok) * CDIM + c],
                               sr_w[c * 8 + i * 4 + j * 2 + k], acc);
                }
        val = acc;
    }
    __shared__ float s_sum[12], s_sq[12];
    float v1 = val, v2 = val * val;
#pragma unroll
    for (int off = 16; off > 0; off >>= 1) {
        v1 += __shfl_xor_sync(0xffffffffu, v1, off);
        v2 += __shfl_xor_sync(0xffffffffu, v2, off);
    }
    int warp = c >> 5, lane = c & 31;
    if (lane == 0) { s_sum[warp] = v1; s_sq[warp] = v2; }
    __syncthreads();
    float tot = 0.f, totsq = 0.f;
#pragma unroll
    for (int w = 0; w < 12; w++) { tot += s_sum[w]; totsq += s_sq[w]; }
    float mu  = tot * (1.0f / CDIM);
    float var = totsq * (1.0f / CDIM) - mu * mu;
    float y = (val - mu) * rsqrtf(var + 1e-5f) * ln_g[c] + ln_b[c];
    g_xr[(size_t)(b * Msr + m) * CDIM + c] = __float2half_rn(y);
}

// ---------------- fp16 TC GEMM, 3-stage cp.async pipeline --------------------
// C[M,N] = A[M,384] @ W[N,384]^T ; BM=64, BN=128, BK=32; 8 warps
// MODE 0: KV epilogue   MODE 1: fp16 out   MODE 2: fp32 + bias
#define GK   384
#define GSTR 40
#define NKIT 12
template<int MODE>
__global__ __launch_bounds__(256)
void gemm_h(const __half* __restrict__ A, const __half* __restrict__ W,
            const float* __restrict__ bias, void* __restrict__ Cout,
            int Md, int Nd) {
    __shared__ __half As[3][64 * GSTR];
    __shared__ __half Ws[3][128 * GSTR];
    int tid = threadIdx.x;
    int warp = tid >> 5, lane = tid & 31;
    int g = lane >> 2, t = lane & 3;
    int wm = warp & 3, wn = warp >> 2;
    int m0 = blockIdx.y * 64, n0 = blockIdx.x * 128;

    int arow = tid >> 2, ac8 = (tid & 3) * 8;

    auto issue = [&](int kk, int s) {
        unsigned au = (unsigned)__cvta_generic_to_shared(&As[s][0]);
        unsigned wu = (unsigned)__cvta_generic_to_shared(&Ws[s][0]);
        cp16(au + (arow * GSTR + ac8) * 2,
             A + (size_t)(m0 + arow) * GK + kk * 32 + ac8);
#pragma unroll
        for (int i = 0; i < 2; i++) {
            int idx = tid + i * 256;
            int wr = idx >> 2, wc = (idx & 3) * 8;
            cp16(wu + (wr * GSTR + wc) * 2,
                 W + (size_t)(n0 + wr) * GK + kk * 32 + wc);
        }
    };

    float acc[8][4] = {};
    issue(0, 0); CPCOMMIT();
    issue(1, 1); CPCOMMIT();

    for (int k = 0; k < NKIT; k++) {
        if (k < NKIT - 1) cpwait<1>(); else cpwait<0>();
        __syncthreads();
        if (k + 2 < NKIT) { issue(k + 2, (k + 2) % 3); CPCOMMIT(); }
        int s = k % 3;
#pragma unroll
        for (int kb = 0; kb < 2; kb++) {
            unsigned a[4];
            const unsigned* ar0 = (const unsigned*)&As[s][(wm * 16 + g) * GSTR + kb * 16];
            const unsigned* ar1 = (const unsigned*)&As[s][(wm * 16 + g + 8) * GSTR + kb * 16];
            a[0] = ar0[t]; a[1] = ar1[t]; a[2] = ar0[t + 4]; a[3] = ar1[t + 4];
#pragma unroll
            for (int nb = 0; nb < 8; nb++) {
                const unsigned* br =
                    (const unsigned*)&Ws[s][(wn * 64 + nb * 8 + g) * GSTR + kb * 16];
                mma_f16(acc[nb], a, br[t], br[t + 4]);
            }
        }
    }

#pragma unroll
    for (int nb = 0; nb < 8; nb++) {
        int col = n0 + wn * 64 + nb * 8 + 2 * t;
        int r = m0 + wm * 16 + g;
        if (MODE == 2) {
            float* C = (float*)Cout;
            float bx = bias[col], by = bias[col + 1];
            if (r < Md)
                *(float2*)&C[(size_t)r * Nd + col] =
                    make_float2(acc[nb][0] + bx, acc[nb][1] + by);
            if (r + 8 < Md)
                *(float2*)&C[(size_t)(r + 8) * Nd + col] =
                    make_float2(acc[nb][2] + bx, acc[nb][3] + by);
        } else if (MODE == 1) {
            __half* C = (__half*)Cout;
            if (r < Md)
                *(unsigned*)&C[(size_t)r * Nd + col] = packh2(acc[nb][0], acc[nb][1]);
            if (r + 8 < Md)
                *(unsigned*)&C[(size_t)(r + 8) * Nd + col] = packh2(acc[nb][2], acc[nb][3]);
        } else {
            if (col < CDIM) {   // K -> key-padded rows
                if (r < Md) {
                    int bb = r / Msr, key = r % Msr;
                    *(unsigned*)&g_kh[(size_t)(bb * KEYPAD + key) * CDIM + col] =
                        packh2(acc[nb][0], acc[nb][1]);
                }
                if (r + 8 < Md) {
                    int bb = (r + 8) / Msr, key = (r + 8) % Msr;
                    *(unsigned*)&g_kh[(size_t)(bb * KEYPAD + key) * CDIM + col] =
                        packh2(acc[nb][2], acc[nb][3]);
                }
            } else {            // V -> transposed scatter
#pragma unroll
                for (int e = 0; e < 4; e++) {
                    int rr = r + (e >= 2 ? 8 : 0);
                    if (rr >= Md) continue;
                    int cc = col + (e & 1);
                    int dall = cc - CDIM;
                    int hh = dall / HD, dd = dall % HD;
                    int bb = rr / Msr, key = rr % Msr;
                    g_vt[(((size_t)(bb * HEADS + hh) * HD) + dd) * KEYPAD + key] =
                        __float2half_rn(acc[nb][e]);
                }
            }
        }
    }
}

// ---------------- fp16 TC flash attention (no-max softmax, 3-stage async) ----
#define NCHUNK 9
#define KSTRH  56
#define VSTRH  72
__global__ __launch_bounds__(256)
void attn_h_kernel() {
    __shared__ __half ks[3][64 * KSTRH];
    __shared__ __half vt[3][HD * VSTRH];

    int tid = threadIdx.x;
    int warp = tid >> 5, lane = tid & 31;
    int g = lane >> 2, t = lane & 3;
    int h = blockIdx.y, b = blockIdx.z;
    int qbase = blockIdx.x * 128 + warp * 16;
    int r0 = qbase + g, r1 = r0 + 8;

    const __half* kbase = g_kh + (size_t)(b * KEYPAD) * CDIM + h * HD;
    const __half* vbase = g_vt + ((size_t)(b * HEADS + h) * HD) * KEYPAD;

    auto issue = [&](int c, int s) {
        const __half* kg = kbase + (size_t)c * 64 * CDIM;
        const __half* vg = vbase + c * 64;
        unsigned ku = (unsigned)__cvta_generic_to_shared(&ks[s][0]);
        unsigned vu = (unsigned)__cvta_generic_to_shared(&vt[s][0]);
#pragma unroll
        for (int i = 0; i < 3; i++) {
            int idx = tid + i * 256;
            if (idx < 384) {
                int key = idx / 6, c8 = (idx % 6) * 8;
                cp16(ku + (key * KSTRH + c8) * 2, kg + (size_t)key * CDIM + c8);
            } else {
                int j = idx - 384, d = j >> 3, c8 = (j & 7) * 8;
                cp16(vu + (d * VSTRH + c8) * 2, vg + (size_t)d * KEYPAD + c8);
            }
        }
    };

    // Q fragments (scale*log2e pre-folded)
    unsigned qf[3][4];
    const __half* qp = g_qh + (size_t)(b * Nq) * CDIM + h * HD;
#pragma unroll
    for (int kb = 0; kb < 3; kb++) {
        int c0 = kb * 16 + 2 * t;
        qf[kb][0] = (r0 < Nq) ? *(const unsigned*)&qp[(size_t)r0 * CDIM + c0] : 0u;
        qf[kb][1] = (r1 < Nq) ? *(const unsigned*)&qp[(size_t)r1 * CDIM + c0] : 0u;
        qf[kb][2] = (r0 < Nq) ? *(const unsigned*)&qp[(size_t)r0 * CDIM + c0 + 8] : 0u;
        qf[kb][3] = (r1 < Nq) ? *(const unsigned*)&qp[(size_t)r1 * CDIM + c0 + 8] : 0u;
    }

    float o[6][4] = {};
    float l0 = 0.f, l1 = 0.f;

    issue(0, 0); CPCOMMIT();
    issue(1, 1); CPCOMMIT();

    for (int c = 0; c < NCHUNK; c++) {
        if (c < NCHUNK - 1) cpwait<1>(); else cpwait<0>();
        __syncthreads();
        if (c + 2 < NCHUNK) { issue(c + 2, (c + 2) % 3); CPCOMMIT(); }
        int s = c % 3;

        // S = Q @ K^T
        float sv[8][4];
#pragma unroll
        for (int nb = 0; nb < 8; nb++) {
            sv[nb][0] = sv[nb][1] = sv[nb][2] = sv[nb][3] = 0.f;
            const unsigned* kr = (const unsigned*)&ks[s][(nb * 8 + g) * KSTRH];
#pragma unroll
            for (int kb = 0; kb < 3; kb++)
                mma_f16(sv[nb], qf[kb], kr[kb * 8 + t], kr[kb * 8 + t + 4]);
        }

        if (c == NCHUNK - 1) {      // mask pad keys (only last chunk has them)
#pragma unroll
            for (int nb = 0; nb < 8; nb++) {
                int key = 512 + nb * 8 + 2 * t;
                if (key >= Msr)     sv[nb][0] = sv[nb][2] = -1e30f;
                if (key + 1 >= Msr) sv[nb][1] = sv[nb][3] = -1e30f;
            }
        }

        // P = 2^S (softmax without max-subtraction; scores are O(1))
        unsigned ph01[8], ph23[8];
#pragma unroll
        for (int nb = 0; nb < 8; nb++) {
            float p0 = ex2(sv[nb][0]);
            float p1 = ex2(sv[nb][1]);
            float p2 = ex2(sv[nb][2]);
            float p3 = ex2(sv[nb][3]);
            l0 += p0 + p1; l1 += p2 + p3;
            ph01[nb] = packh2(p0, p1);
            ph23[nb] = packh2(p2, p3);
        }

        // O += P @ V
#pragma unroll
        for (int kb = 0; kb < 4; kb++) {
            unsigned a[4] = {ph01[2 * kb], ph23[2 * kb],
                             ph01[2 * kb + 1], ph23[2 * kb + 1]};
#pragma unroll
            for (int nb = 0; nb < 6; nb++) {
                const unsigned* vr = (const unsigned*)&vt[s][(nb * 8 + g) * VSTRH];
                mma_f16(o[nb], a, vr[kb * 8 + t], vr[kb * 8 + t + 4]);
            }
        }
    }

    // single final row-sum reduction across the t-quads
    l0 += __shfl_xor_sync(0xffffffffu, l0, 1);
    l0 += __shfl_xor_sync(0xffffffffu, l0, 2);
    l1 += __shfl_xor_sync(0xffffffffu, l1, 1);
    l1 += __shfl_xor_sync(0xffffffffu, l1, 2);

    float i0 = 1.f / l0, i1 = 1.f / l1;
    __half* op = g_ah + (size_t)(b * Nq) * CDIM + h * HD;
#pragma unroll
    for (int nb = 0; nb < 6; nb++) {
        int col = nb * 8 + 2 * t;
        if (r0 < Nq)
            *(unsigned*)&op[(size_t)r0 * CDIM + col] = packh2(o[nb][0] * i0, o[nb][1] * i0);
        if (r1 < Nq)
            *(unsigned*)&op[(size_t)r1 * CDIM + col] = packh2(o[nb][2] * i1, o[nb][3] * i1);
    }
}

// ---------------- launcher ---------------------------------------------------
extern "C" void kernel_launch(void* const* d_in, const int* in_sizes, int n_in,
                              void* d_out, int out_size) {
    const float* x      = (const float*)d_in[0];
    const float* q_w    = (const float*)d_in[1];
    const float* kv_w   = (const float*)d_in[2];
    const float* proj_w = (const float*)d_in[3];
    const float* proj_b = (const float*)d_in[4];
    const float* sr_w   = (const float*)d_in[5];
    const float* sr_b   = (const float*)d_in[6];
    const float* ln_g   = (const float*)d_in[7];
    const float* ln_b   = (const float*)d_in[8];
    float* out = (float*)d_out;

    __half *xh, *qh, *ah, *xr, *wh;
    cudaGetSymbolAddress((void**)&xh, g_xh);
    cudaGetSymbolAddress((void**)&qh, g_qh);
    cudaGetSymbolAddress((void**)&ah, g_ah);
    cudaGetSymbolAddress((void**)&xr, g_xr);
    cudaGetSymbolAddress((void**)&wh, g_wh);

    const int Mq = Bz * Nq;        // 16388
    const int Mr = Bz * Msr;       // 2052
    const int CV = XC4 + QC4 + KC4 + PC4;

    // 0. one merged fp32->fp16 conversion pass (scale*log2e folded into q_w)
    cvt_all<<<(CV + 255) / 256, 256>>>(x, q_w, kv_w, proj_w);
    // 1. reduced tokens + LN (fp16 out)
    reduce_ln_kernel<<<dim3(Msr, Bz), 384>>>(x, sr_w, sr_b, ln_g, ln_b);
    // 2. kv projection -> key-padded K + V^T scatter
    gemm_h<0><<<dim3(768 / 128, (Mr + 63) / 64), 256>>>(
        xr, wh + 147456, nullptr, nullptr, Mr, 2 * CDIM);
    // 3. q projection
    gemm_h<1><<<dim3(CDIM / 128, (Mq + 63) / 64), 256>>>(
        xh, wh, nullptr, qh, Mq, CDIM);
    // 4. attention
    attn_h_kernel<<<dim3((Nq + 127) / 128, HEADS, Bz), 256>>>();
    // 5. output projection + bias (fp32 out)
    gemm_h<2><<<dim3(CDIM / 128, (Mq + 63) / 64), 256>>>(
        ah, wh + 442368, proj_b, out, Mq, CDIM);
}

// round 7
// speedup vs baseline: 2.5050x; 1.1001x over previous
#include <cuda_runtime.h>
#include <cuda_fp16.h>
#include <cstdint>
#include <math.h>

#define Bz     4
#define Nq     4097
#define CDIM   384
#define HEADS  8
#define HD     48
#define Msr    513
#define KEYPAD 576
#define MPAD   16512        // padded query rows (mult of 128)
#define MRPAD  2176         // padded reduced rows (mult of 128)

// ---------------- scratch (static device globals; zero-init, no allocs) -----
__device__ __half g_xh[(size_t)MPAD * CDIM];            // x fp16
__device__ __half g_qh[(size_t)MPAD * CDIM];            // q (scale*log2e folded)
__device__ __half g_ah[(size_t)MPAD * CDIM];            // attention out fp16
__device__ __half g_xr[(size_t)MRPAD * CDIM];           // reduced+LN tokens
__device__ __half g_kh[(size_t)Bz * KEYPAD * CDIM];     // K fp16, key-padded
__device__ __half g_vt[(size_t)Bz * HEADS * HD * KEYPAD]; // V^T fp16
__device__ __half g_wh[589824];                         // q_w*sc | kv_w | proj_w

// ---------------- helpers ----------------------------------------------------
__device__ __forceinline__ unsigned packh2(float x, float y) {
    __half2 h = __floats2half2_rn(x, y);
    return *(unsigned*)&h;
}
__device__ __forceinline__ float ex2(float x) {
    float y;
    asm("ex2.approx.ftz.f32 %0, %1;" : "=f"(y) : "f"(x));
    return y;
}
__device__ __forceinline__ void mma_f16(float* d, const unsigned* a,
                                        unsigned b0, unsigned b1) {
    asm volatile(
        "mma.sync.aligned.m16n8k16.row.col.f32.f16.f16.f32 "
        "{%0,%1,%2,%3}, {%4,%5,%6,%7}, {%8,%9}, {%0,%1,%2,%3};"
        : "+f"(d[0]), "+f"(d[1]), "+f"(d[2]), "+f"(d[3])
        : "r"(a[0]), "r"(a[1]), "r"(a[2]), "r"(a[3]), "r"(b0), "r"(b1));
}
__device__ __forceinline__ void ldsm4(unsigned& r0, unsigned& r1,
                                      unsigned& r2, unsigned& r3, unsigned addr) {
    asm volatile("ldmatrix.sync.aligned.m8n8.x4.shared.b16 {%0,%1,%2,%3}, [%4];"
                 : "=r"(r0), "=r"(r1), "=r"(r2), "=r"(r3) : "r"(addr));
}
__device__ __forceinline__ void cp16(unsigned s, const void* g) {
    asm volatile("cp.async.cg.shared.global [%0], [%1], 16;" :: "r"(s), "l"(g));
}
#define CPCOMMIT() asm volatile("cp.async.commit_group;" ::: "memory")
template<int N>
__device__ __forceinline__ void cpwait() {
    asm volatile("cp.async.wait_group %0;" :: "n"(N) : "memory");
}

// ---------------- merged fp32 -> fp16 conversion -----------------------------
#define XC4 ((Bz * Nq * CDIM) / 4)
#define QC4 36864
#define KC4 73728
#define PC4 36864
__global__ __launch_bounds__(256)
void cvt_all(const float* __restrict__ x, const float* __restrict__ qw,
             const float* __restrict__ kvw, const float* __restrict__ pw) {
    int j = blockIdx.x * 256 + threadIdx.x;
    const float* s; __half* d;
    float sc = 1.f;
    if (j < XC4) { s = x; d = g_xh; }
    else {
        j -= XC4;
        if (j < QC4) { s = qw; d = g_wh;
                       sc = 0.14433756729740644f * 1.4426950408889634f; }
        else {
            j -= QC4;
            if (j < KC4) { s = kvw; d = g_wh + 147456; }
            else { j -= KC4; if (j >= PC4) return; s = pw; d = g_wh + 442368; }
        }
    }
    float4 v = *(const float4*)&s[(size_t)j * 4];
    uint2 u = make_uint2(packh2(v.x * sc, v.y * sc), packh2(v.z * sc, v.w * sc));
    *(uint2*)&d[(size_t)j * 4] = u;
}

// ---------------- fused depthwise-conv(2x2x2,s2) + CLS + LayerNorm ----------
__global__ __launch_bounds__(384)
void reduce_ln_kernel(const float* __restrict__ x,
                      const float* __restrict__ sr_w,
                      const float* __restrict__ sr_b,
                      const float* __restrict__ ln_g,
                      const float* __restrict__ ln_b) {
    int m = blockIdx.x, b = blockIdx.y, c = threadIdx.x;
    float val;
    if (m == 0) {
        val = x[(size_t)(b * Nq) * CDIM + c];
    } else {
        int p  = m - 1;
        int z0 = p >> 6, z1 = (p >> 3) & 7, z2 = p & 7;
        int base = 1 + (2 * z0) * 256 + (2 * z1) * 16 + (2 * z2);
        float acc = sr_b[c];
#pragma unroll
        for (int i = 0; i < 2; i++)
#pragma unroll
            for (int j = 0; j < 2; j++)
#pragma unroll
                for (int k = 0; k < 2; k++) {
                    int tok = base + i * 256 + j * 16 + k;
                    acc = fmaf(x[(size_t)(b * Nq + tok) * CDIM + c],
                               sr_w[c * 8 + i * 4 + j * 2 + k], acc);
                }
        val = acc;
    }
    __shared__ float s_sum[12], s_sq[12];
    float v1 = val, v2 = val * val;
#pragma unroll
    for (int off = 16; off > 0; off >>= 1) {
        v1 += __shfl_xor_sync(0xffffffffu, v1, off);
        v2 += __shfl_xor_sync(0xffffffffu, v2, off);
    }
    int warp = c >> 5, lane = c & 31;
    if (lane == 0) { s_sum[warp] = v1; s_sq[warp] = v2; }
    __syncthreads();
    float tot = 0.f, totsq = 0.f;
#pragma unroll
    for (int w = 0; w < 12; w++) { tot += s_sum[w]; totsq += s_sq[w]; }
    float mu  = tot * (1.0f / CDIM);
    float var = totsq * (1.0f / CDIM) - mu * mu;
    float y = (val - mu) * rsqrtf(var + 1e-5f) * ln_g[c] + ln_b[c];
    g_xr[(size_t)(b * Msr + m) * CDIM + c] = __float2half_rn(y);
}

// ---------------- fp16 TC GEMM, BM=128 BN=128 BK=32, 3-stage, ldmatrix ------
// MODE 0: KV epilogue   MODE 1: fp16 out   MODE 2: fp32 + bias
#define GK     384
#define GSTR   40
#define GSTAGE (256 * GSTR)     // halves per stage (A 128*40 + W 128*40)
#define NKIT   12
template<int MODE>
__global__ __launch_bounds__(256)
void gemm_h(const __half* __restrict__ A, const __half* __restrict__ W,
            const float* __restrict__ bias, void* __restrict__ Cout,
            int Md, int Nd) {
    extern __shared__ __half sh[];
    int tid = threadIdx.x;
    int warp = tid >> 5, lane = tid & 31;
    int g = lane >> 2, t = lane & 3;
    int wm = warp & 3, wn = warp >> 2;
    int m0 = blockIdx.y * 128, n0 = blockIdx.x * 128;

    unsigned smbase = (unsigned)__cvta_generic_to_shared(sh);
    int li = lane & 7, seg = lane >> 3;
    int a_row = (seg & 1) * 8 + li, a_k = (seg >> 1) * 8;
    int b_row = (seg >> 1) * 8 + li, b_k = (seg & 1) * 8;

    auto issue = [&](int kk, int s) {
        unsigned sb = smbase + s * (GSTAGE * 2);
#pragma unroll
        for (int i = 0; i < 2; i++) {
            int idx = tid + i * 256;
            int row = idx >> 2, c8 = (idx & 3) * 8;
            cp16(sb + (row * GSTR + c8) * 2,
                 A + (size_t)(m0 + row) * GK + kk * 32 + c8);
            cp16(sb + ((128 + row) * GSTR + c8) * 2,
                 W + (size_t)(n0 + row) * GK + kk * 32 + c8);
        }
    };

    float acc[2][8][4] = {};
    issue(0, 0); CPCOMMIT();
    issue(1, 1); CPCOMMIT();

    for (int k = 0; k < NKIT; k++) {
        if (k < NKIT - 1) cpwait<1>(); else cpwait<0>();
        __syncthreads();
        if (k + 2 < NKIT) { issue(k + 2, (k + 2) % 3); CPCOMMIT(); }
        unsigned sb = smbase + (k % 3) * (GSTAGE * 2);
#pragma unroll
        for (int kb = 0; kb < 2; kb++) {
            unsigned a[2][4];
#pragma unroll
            for (int mf = 0; mf < 2; mf++)
                ldsm4(a[mf][0], a[mf][1], a[mf][2], a[mf][3],
                      sb + ((wm * 32 + mf * 16 + a_row) * GSTR + kb * 16 + a_k) * 2);
#pragma unroll
            for (int np = 0; np < 4; np++) {
                unsigned b0, b1, b2, b3;
                ldsm4(b0, b1, b2, b3,
                      sb + ((128 + wn * 64 + np * 16 + b_row) * GSTR + kb * 16 + b_k) * 2);
#pragma unroll
                for (int mf = 0; mf < 2; mf++) {
                    mma_f16(acc[mf][2 * np], a[mf], b0, b1);
                    mma_f16(acc[mf][2 * np + 1], a[mf], b2, b3);
                }
            }
        }
    }

#pragma unroll
    for (int mf = 0; mf < 2; mf++) {
#pragma unroll
        for (int nb = 0; nb < 8; nb++) {
            int col = n0 + wn * 64 + nb * 8 + 2 * t;
            int r = m0 + wm * 32 + mf * 16 + g;
            float* ac = acc[mf][nb];
            if (MODE == 2) {
                float* C = (float*)Cout;
                float bx = bias[col], by = bias[col + 1];
                if (r < Md)
                    *(float2*)&C[(size_t)r * Nd + col] =
                        make_float2(ac[0] + bx, ac[1] + by);
                if (r + 8 < Md)
                    *(float2*)&C[(size_t)(r + 8) * Nd + col] =
                        make_float2(ac[2] + bx, ac[3] + by);
            } else if (MODE == 1) {
                __half* C = (__half*)Cout;
                if (r < Md)
                    *(unsigned*)&C[(size_t)r * Nd + col] = packh2(ac[0], ac[1]);
                if (r + 8 < Md)
                    *(unsigned*)&C[(size_t)(r + 8) * Nd + col] = packh2(ac[2], ac[3]);
            } else {
                if (col < CDIM) {   // K -> key-padded rows
                    if (r < Md) {
                        int bb = r / Msr, key = r % Msr;
                        *(unsigned*)&g_kh[(size_t)(bb * KEYPAD + key) * CDIM + col] =
                            packh2(ac[0], ac[1]);
                    }
                    if (r + 8 < Md) {
                        int bb = (r + 8) / Msr, key = (r + 8) % Msr;
                        *(unsigned*)&g_kh[(size_t)(bb * KEYPAD + key) * CDIM + col] =
                            packh2(ac[2], ac[3]);
                    }
                } else {            // V -> transposed scatter
#pragma unroll
                    for (int e = 0; e < 4; e++) {
                        int rr = r + (e >= 2 ? 8 : 0);
                        if (rr >= Md) continue;
                        int cc = col + (e & 1);
                        int dall = cc - CDIM;
                        int hh = dall / HD, dd = dall % HD;
                        int bb = rr / Msr, key = rr % Msr;
                        g_vt[(((size_t)(bb * HEADS + hh) * HD) + dd) * KEYPAD + key] =
                            __float2half_rn(ac[e]);
                    }
                }
            }
        }
    }
}

// ---------------- fp16 TC flash attention (no-max softmax, ldmatrix) --------
#define NCHUNK 9
#define KSTRH  56
#define VSTRH  72
#define KSZ    (64 * KSTRH)
#define VSZ    (HD * VSTRH)
__global__ __launch_bounds__(256)
void attn_h_kernel() {
    __shared__ __half ks[3][KSZ];
    __shared__ __half vt[3][VSZ];

    int tid = threadIdx.x;
    int warp = tid >> 5, lane = tid & 31;
    int g = lane >> 2, t = lane & 3;
    int li = lane & 7, seg = lane >> 3;
    int b_row = (seg >> 1) * 8 + li, b_k = (seg & 1) * 8;
    int h = blockIdx.y, b = blockIdx.z;
    int qbase = blockIdx.x * 128 + warp * 16;
    int r0 = qbase + g, r1 = r0 + 8;

    const __half* kbase = g_kh + (size_t)(b * KEYPAD) * CDIM + h * HD;
    const __half* vbase = g_vt + ((size_t)(b * HEADS + h) * HD) * KEYPAD;
    unsigned ksb = (unsigned)__cvta_generic_to_shared(&ks[0][0]);
    unsigned vtb = (unsigned)__cvta_generic_to_shared(&vt[0][0]);

    auto issue = [&](int c, int s) {
        const __half* kg = kbase + (size_t)c * 64 * CDIM;
        const __half* vg = vbase + c * 64;
        unsigned ku = ksb + s * (KSZ * 2);
        unsigned vu = vtb + s * (VSZ * 2);
#pragma unroll
        for (int i = 0; i < 3; i++) {
            int idx = tid + i * 256;
            if (idx < 384) {
                int key = idx / 6, c8 = (idx % 6) * 8;
                cp16(ku + (key * KSTRH + c8) * 2, kg + (size_t)key * CDIM + c8);
            } else {
                int j = idx - 384, d = j >> 3, c8 = (j & 7) * 8;
                cp16(vu + (d * VSTRH + c8) * 2, vg + (size_t)d * KEYPAD + c8);
            }
        }
    };

    // Q fragments (scale*log2e pre-folded)
    unsigned qf[3][4];
    const __half* qp = g_qh + (size_t)(b * Nq) * CDIM + h * HD;
#pragma unroll
    for (int kb = 0; kb < 3; kb++) {
        int c0 = kb * 16 + 2 * t;
        qf[kb][0] = (r0 < Nq) ? *(const unsigned*)&qp[(size_t)r0 * CDIM + c0] : 0u;
        qf[kb][1] = (r1 < Nq) ? *(const unsigned*)&qp[(size_t)r1 * CDIM + c0] : 0u;
        qf[kb][2] = (r0 < Nq) ? *(const unsigned*)&qp[(size_t)r0 * CDIM + c0 + 8] : 0u;
        qf[kb][3] = (r1 < Nq) ? *(const unsigned*)&qp[(size_t)r1 * CDIM + c0 + 8] : 0u;
    }

    float o[6][4] = {};
    float l0 = 0.f, l1 = 0.f;

    issue(0, 0); CPCOMMIT();
    issue(1, 1); CPCOMMIT();

    for (int c = 0; c < NCHUNK; c++) {
        if (c < NCHUNK - 1) cpwait<1>(); else cpwait<0>();
        __syncthreads();
        if (c + 2 < NCHUNK) { issue(c + 2, (c + 2) % 3); CPCOMMIT(); }
        int s = c % 3;
        unsigned ku = ksb + s * (KSZ * 2);
        unsigned vu = vtb + s * (VSZ * 2);

        // S = Q @ K^T (12 ldmatrix.x4 + 24 mma)
        float sv[8][4] = {};
#pragma unroll
        for (int kb = 0; kb < 3; kb++) {
#pragma unroll
            for (int np = 0; np < 4; np++) {
                unsigned b0, b1, b2, b3;
                ldsm4(b0, b1, b2, b3,
                      ku + ((np * 16 + b_row) * KSTRH + kb * 16 + b_k) * 2);
                mma_f16(sv[2 * np], qf[kb], b0, b1);
                mma_f16(sv[2 * np + 1], qf[kb], b2, b3);
            }
        }

        if (c == NCHUNK - 1) {      // mask pad keys (only last chunk)
#pragma unroll
            for (int nb = 0; nb < 8; nb++) {
                int key = 512 + nb * 8 + 2 * t;
                if (key >= Msr)     sv[nb][0] = sv[nb][2] = -1e30f;
                if (key + 1 >= Msr) sv[nb][1] = sv[nb][3] = -1e30f;
            }
        }

        // P = 2^S
        unsigned ph01[8], ph23[8];
#pragma unroll
        for (int nb = 0; nb < 8; nb++) {
            float p0 = ex2(sv[nb][0]);
            float p1 = ex2(sv[nb][1]);
            float p2 = ex2(sv[nb][2]);
            float p3 = ex2(sv[nb][3]);
            l0 += p0 + p1; l1 += p2 + p3;
            ph01[nb] = packh2(p0, p1);
            ph23[nb] = packh2(p2, p3);
        }

        // O += P @ V (12 ldmatrix.x4 + 24 mma)
#pragma unroll
        for (int kb = 0; kb < 4; kb++) {
            unsigned a[4] = {ph01[2 * kb], ph23[2 * kb],
                             ph01[2 * kb + 1], ph23[2 * kb + 1]};
#pragma unroll
            for (int np = 0; np < 3; np++) {
                unsigned b0, b1, b2, b3;
                ldsm4(b0, b1, b2, b3,
                      vu + ((np * 16 + b_row) * VSTRH + kb * 16 + b_k) * 2);
                mma_f16(o[2 * np], a, b0, b1);
                mma_f16(o[2 * np + 1], a, b2, b3);
            }
        }
    }

    l0 += __shfl_xor_sync(0xffffffffu, l0, 1);
    l0 += __shfl_xor_sync(0xffffffffu, l0, 2);
    l1 += __shfl_xor_sync(0xffffffffu, l1, 1);
    l1 += __shfl_xor_sync(0xffffffffu, l1, 2);

    float i0 = 1.f / l0, i1 = 1.f / l1;
    __half* op = g_ah + (size_t)(b * Nq) * CDIM + h * HD;
#pragma unroll
    for (int nb = 0; nb < 6; nb++) {
        int col = nb * 8 + 2 * t;
        if (r0 < Nq)
            *(unsigned*)&op[(size_t)r0 * CDIM + col] = packh2(o[nb][0] * i0, o[nb][1] * i0);
        if (r1 < Nq)
            *(unsigned*)&op[(size_t)r1 * CDIM + col] = packh2(o[nb][2] * i1, o[nb][3] * i1);
    }
}

// ---------------- launcher ---------------------------------------------------
extern "C" void kernel_launch(void* const* d_in, const int* in_sizes, int n_in,
                              void* d_out, int out_size) {
    const float* x      = (const float*)d_in[0];
    const float* q_w    = (const float*)d_in[1];
    const float* kv_w   = (const float*)d_in[2];
    const float* proj_w = (const float*)d_in[3];
    const float* proj_b = (const float*)d_in[4];
    const float* sr_w   = (const float*)d_in[5];
    const float* sr_b   = (const float*)d_in[6];
    const float* ln_g   = (const float*)d_in[7];
    const float* ln_b   = (const float*)d_in[8];
    float* out = (float*)d_out;

    __half *xh, *qh, *ah, *xr, *wh;
    cudaGetSymbolAddress((void**)&xh, g_xh);
    cudaGetSymbolAddress((void**)&qh, g_qh);
    cudaGetSymbolAddress((void**)&ah, g_ah);
    cudaGetSymbolAddress((void**)&xr, g_xr);
    cudaGetSymbolAddress((void**)&wh, g_wh);

    const int Mq = Bz * Nq;        // 16388
    const int Mr = Bz * Msr;       // 2052
    const int CV = XC4 + QC4 + KC4 + PC4;
    const int gsmem = 3 * GSTAGE * 2;   // 61440 B

    cudaFuncSetAttribute(gemm_h<0>, cudaFuncAttributeMaxDynamicSharedMemorySize, gsmem);
    cudaFuncSetAttribute(gemm_h<1>, cudaFuncAttributeMaxDynamicSharedMemorySize, gsmem);
    cudaFuncSetAttribute(gemm_h<2>, cudaFuncAttributeMaxDynamicSharedMemorySize, gsmem);

    // 0. one merged fp32->fp16 conversion pass
    cvt_all<<<(CV + 255) / 256, 256>>>(x, q_w, kv_w, proj_w);
    // 1. reduced tokens + LN (fp16 out)
    reduce_ln_kernel<<<dim3(Msr, Bz), 384>>>(x, sr_w, sr_b, ln_g, ln_b);
    // 2. kv projection -> key-padded K + V^T scatter
    gemm_h<0><<<dim3(768 / 128, (Mr + 127) / 128), 256, gsmem>>>(
        xr, wh + 147456, nullptr, nullptr, Mr, 2 * CDIM);
    // 3. q projection
    gemm_h<1><<<dim3(CDIM / 128, (Mq + 127) / 128), 256, gsmem>>>(
        xh, wh, nullptr, qh, Mq, CDIM);
    // 4. attention
    attn_h_kernel<<<dim3((Nq + 127) / 128, HEADS, Bz), 256>>>();
    // 5. output projection + bias (fp32 out)
    gemm_h<2><<<dim3(CDIM / 128, (Mq + 127) / 128), 256, gsmem>>>(
        ah, wh + 442368, proj_b, out, Mq, CDIM);
}